// round 1
// baseline (speedup 1.0000x reference)
#include <cuda_runtime.h>
#include <cstdint>

// Problem constants
#define BATCH   32
#define HW      56          // H = W = 56
#define CCH     192         // channels
#define WS      7
#define NWIN1D  8           // 56/7
#define NW      49          // tokens per window
#define BW      2048        // BATCH * 8 * 8 windows
#define HEADS   6
#define DH      32          // head dim
#define MTOK    100352      // BATCH*HW*HW = BW*NW
#define QKV_N   576         // 3*C

// Scratch (device globals — allocation-free)
__device__ float g_xw[(size_t)BW * NW * CCH];            // 77 MB  LN'd, window-partitioned
__device__ float g_qkv[(size_t)3 * BW * HEADS * NW * DH]; // 231 MB [s][w][h][n][d]
__device__ float g_att[(size_t)BW * NW * CCH];            // 77 MB  attention output, window order

// ---------------------------------------------------------------------------
// Kernel 1: LayerNorm + window partition. One warp per token.
// ---------------------------------------------------------------------------
__global__ void ln_partition_kernel(const float* __restrict__ x,
                                    const float* __restrict__ gamma) {
    int t    = blockIdx.x * 8 + (threadIdx.x >> 5);
    int lane = threadIdx.x & 31;
    const float* xp = x + (size_t)t * CCH;

    float v[6];
    float s = 0.f, sq = 0.f;
#pragma unroll
    for (int i = 0; i < 6; i++) {
        v[i] = xp[lane + 32 * i];
        s  += v[i];
        sq += v[i] * v[i];
    }
#pragma unroll
    for (int off = 16; off > 0; off >>= 1) {
        s  += __shfl_xor_sync(0xFFFFFFFFu, s,  off);
        sq += __shfl_xor_sync(0xFFFFFFFFu, sq, off);
    }
    float mu  = s  * (1.0f / CCH);
    float var = sq * (1.0f / CCH) - mu * mu;
    float rs  = rsqrtf(var + 1e-5f);

    int b  = t / 3136;
    int rc = t % 3136;
    int r  = rc / HW, c = rc % HW;
    int wr = r / WS, ir = r % WS;
    int wc = c / WS, ic = c % WS;
    int w  = (b * NWIN1D + wr) * NWIN1D + wc;
    int n  = ir * WS + ic;

    float* dst = g_xw + ((size_t)w * NW + n) * CCH;
#pragma unroll
    for (int i = 0; i < 6; i++) {
        int ch = lane + 32 * i;
        dst[ch] = (v[i] - mu) * rs * gamma[ch];
    }
}

// ---------------------------------------------------------------------------
// Kernel 2: QKV GEMM.  C[M=100352, N=576] = g_xw[M,192] @ qkv_w[576,192]^T + b
// 64x64 tile, BK=16, 256 threads, 4x4 per thread. Epilogue scatters to
// g_qkv[s][w][head][n][d].
// ---------------------------------------------------------------------------
__global__ void __launch_bounds__(256) gemm_qkv_kernel(const float* __restrict__ W,
                                                       const float* __restrict__ bias) {
    __shared__ float As[16][64];
    __shared__ float Bs[16][64];

    int tid = threadIdx.x;
    int tx = tid & 15, ty = tid >> 4;
    int bx = blockIdx.x, by = blockIdx.y;

    const float* Ag = g_xw + (size_t)(by * 64) * CCH;
    const float* Bg = W    + (size_t)(bx * 64) * CCH;

    int lm = tid >> 2;         // 0..63 row within tile
    int lk = (tid & 3) * 4;    // 0,4,8,12

    float acc[4][4] = {};

    for (int kt = 0; kt < CCH; kt += 16) {
        float4 av = *(const float4*)(Ag + (size_t)lm * CCH + kt + lk);
        float4 bv = *(const float4*)(Bg + (size_t)lm * CCH + kt + lk);
        As[lk + 0][lm] = av.x; As[lk + 1][lm] = av.y;
        As[lk + 2][lm] = av.z; As[lk + 3][lm] = av.w;
        Bs[lk + 0][lm] = bv.x; Bs[lk + 1][lm] = bv.y;
        Bs[lk + 2][lm] = bv.z; Bs[lk + 3][lm] = bv.w;
        __syncthreads();
#pragma unroll
        for (int k = 0; k < 16; k++) {
            float4 a = *(const float4*)&As[k][ty * 4];
            float4 b = *(const float4*)&Bs[k][tx * 4];
            acc[0][0] += a.x * b.x; acc[0][1] += a.x * b.y; acc[0][2] += a.x * b.z; acc[0][3] += a.x * b.w;
            acc[1][0] += a.y * b.x; acc[1][1] += a.y * b.y; acc[1][2] += a.y * b.z; acc[1][3] += a.y * b.w;
            acc[2][0] += a.z * b.x; acc[2][1] += a.z * b.y; acc[2][2] += a.z * b.z; acc[2][3] += a.z * b.w;
            acc[3][0] += a.w * b.x; acc[3][1] += a.w * b.y; acc[3][2] += a.w * b.z; acc[3][3] += a.w * b.w;
        }
        __syncthreads();
    }

    int m0 = by * 64 + ty * 4;
    int j0 = bx * 64 + tx * 4;
    float bv[4];
#pragma unroll
    for (int j = 0; j < 4; j++) bv[j] = bias[j0 + j];

#pragma unroll
    for (int i = 0; i < 4; i++) {
        int m = m0 + i;
        int w = m / NW, n = m % NW;
#pragma unroll
        for (int j = 0; j < 4; j++) {
            int jc   = j0 + j;
            int s    = jc / CCH;
            int rem  = jc % CCH;
            int head = rem / DH;
            int dd   = rem % DH;
            g_qkv[(((size_t)s * BW + w) * HEADS + head) * (NW * DH) + n * DH + dd] =
                acc[i][j] + bv[j];
        }
    }
}

// ---------------------------------------------------------------------------
// Kernel 3: attention per (window, head). 128 threads.
// ---------------------------------------------------------------------------
__global__ void __launch_bounds__(128) attn_kernel(const float* __restrict__ rpb) {
    int w    = blockIdx.x;
    int head = blockIdx.y;
    int tid  = threadIdx.x;
    int lane = tid & 31;
    int wid  = tid >> 5;

    __shared__ float qS[NW * 33];
    __shared__ float kS[NW * 33];
    __shared__ float vS[NW * 33];
    __shared__ float aS[NW * NW];
    __shared__ float biasS[169];

    size_t base = ((size_t)w * HEADS + head) * (NW * DH);
    const float* qg = g_qkv + base;
    const float* kg = g_qkv + (size_t)BW * HEADS * NW * DH + base;
    const float* vg = g_qkv + (size_t)2 * BW * HEADS * NW * DH + base;

    for (int i = tid; i < NW * DH; i += 128) {
        int n = i >> 5, c = i & 31;
        qS[n * 33 + c] = qg[i];
        kS[n * 33 + c] = kg[i];
        vS[n * 33 + c] = vg[i];
    }
    for (int i = tid; i < 169; i += 128) biasS[i] = rpb[i * HEADS + head];
    __syncthreads();

    const float scale = 0.17677669529663687f;  // 1/sqrt(32)
    int m0 = lane;
    int m1 = lane + 32;
    bool v1 = (m1 < NW);
    int m1c = v1 ? m1 : 0;
    int jr0 = m0 / WS, jc0 = m0 % WS;
    int jr1 = m1c / WS, jc1 = m1c % WS;

    for (int n = wid; n < NW; n += 4) {
        float a0 = 0.f, a1 = 0.f;
#pragma unroll
        for (int k = 0; k < DH; k++) {
            float qv = qS[n * 33 + k];
            a0 += qv * kS[m0 * 33 + k];
            a1 += qv * kS[m1c * 33 + k];
        }
        int ir = n / WS, ic = n % WS;
        float s0 = a0 * scale + biasS[(ir - jr0 + 6) * 13 + (ic - jc0 + 6)];
        float s1 = v1 ? (a1 * scale + biasS[(ir - jr1 + 6) * 13 + (ic - jc1 + 6)])
                      : -1e30f;
        float mx = fmaxf(s0, s1);
#pragma unroll
        for (int off = 16; off > 0; off >>= 1)
            mx = fmaxf(mx, __shfl_xor_sync(0xFFFFFFFFu, mx, off));
        float e0 = expf(s0 - mx);
        float e1 = v1 ? expf(s1 - mx) : 0.f;
        float sm = e0 + e1;
#pragma unroll
        for (int off = 16; off > 0; off >>= 1)
            sm += __shfl_xor_sync(0xFFFFFFFFu, sm, off);
        float inv = 1.0f / sm;
        aS[n * NW + m0] = e0 * inv;
        if (v1) aS[n * NW + m1] = e1 * inv;
    }
    __syncwarp();

    for (int n = wid; n < NW; n += 4) {
        float acc = 0.f;
#pragma unroll
        for (int m = 0; m < NW; m++)
            acc += aS[n * NW + m] * vS[m * 33 + lane];
        g_att[((size_t)w * NW + n) * CCH + head * DH + lane] = acc;
    }
}

// ---------------------------------------------------------------------------
// Kernel 4: proj GEMM + window reverse.
// out[t, j] = g_att[m, :] @ proj_w[j, :] + proj_b[j], m -> t remap.
// ---------------------------------------------------------------------------
__global__ void __launch_bounds__(256) gemm_proj_kernel(const float* __restrict__ W,
                                                        const float* __restrict__ bias,
                                                        float* __restrict__ out) {
    __shared__ float As[16][64];
    __shared__ float Bs[16][64];

    int tid = threadIdx.x;
    int tx = tid & 15, ty = tid >> 4;
    int bx = blockIdx.x, by = blockIdx.y;

    const float* Ag = g_att + (size_t)(by * 64) * CCH;
    const float* Bg = W     + (size_t)(bx * 64) * CCH;

    int lm = tid >> 2;
    int lk = (tid & 3) * 4;

    float acc[4][4] = {};

    for (int kt = 0; kt < CCH; kt += 16) {
        float4 av = *(const float4*)(Ag + (size_t)lm * CCH + kt + lk);
        float4 bv = *(const float4*)(Bg + (size_t)lm * CCH + kt + lk);
        As[lk + 0][lm] = av.x; As[lk + 1][lm] = av.y;
        As[lk + 2][lm] = av.z; As[lk + 3][lm] = av.w;
        Bs[lk + 0][lm] = bv.x; Bs[lk + 1][lm] = bv.y;
        Bs[lk + 2][lm] = bv.z; Bs[lk + 3][lm] = bv.w;
        __syncthreads();
#pragma unroll
        for (int k = 0; k < 16; k++) {
            float4 a = *(const float4*)&As[k][ty * 4];
            float4 b = *(const float4*)&Bs[k][tx * 4];
            acc[0][0] += a.x * b.x; acc[0][1] += a.x * b.y; acc[0][2] += a.x * b.z; acc[0][3] += a.x * b.w;
            acc[1][0] += a.y * b.x; acc[1][1] += a.y * b.y; acc[1][2] += a.y * b.z; acc[1][3] += a.y * b.w;
            acc[2][0] += a.z * b.x; acc[2][1] += a.z * b.y; acc[2][2] += a.z * b.z; acc[2][3] += a.z * b.w;
            acc[3][0] += a.w * b.x; acc[3][1] += a.w * b.y; acc[3][2] += a.w * b.z; acc[3][3] += a.w * b.w;
        }
        __syncthreads();
    }

    int m0 = by * 64 + ty * 4;
    int j0 = bx * 64 + tx * 4;
    float bv[4];
#pragma unroll
    for (int j = 0; j < 4; j++) bv[j] = bias[j0 + j];

#pragma unroll
    for (int i = 0; i < 4; i++) {
        int m = m0 + i;
        int w = m / NW, n = m % NW;
        int b  = w / 64;
        int wr = (w % 64) / NWIN1D;
        int wc = w % NWIN1D;
        int r  = wr * WS + n / WS;
        int c  = wc * WS + n % WS;
        size_t t = (size_t)b * 3136 + r * HW + c;
#pragma unroll
        for (int j = 0; j < 4; j++) {
            out[t * CCH + j0 + j] = acc[i][j] + bv[j];
        }
    }
}

// ---------------------------------------------------------------------------
extern "C" void kernel_launch(void* const* d_in, const int* in_sizes, int n_in,
                              void* d_out, int out_size) {
    const float* x      = (const float*)d_in[0];
    const float* gamma  = (const float*)d_in[1];
    const float* rpb    = (const float*)d_in[2];
    const float* qkv_w  = (const float*)d_in[3];
    const float* qkv_b  = (const float*)d_in[4];
    const float* proj_w = (const float*)d_in[5];
    const float* proj_b = (const float*)d_in[6];
    float* out = (float*)d_out;

    ln_partition_kernel<<<MTOK / 8, 256>>>(x, gamma);
    gemm_qkv_kernel<<<dim3(QKV_N / 64, MTOK / 64), 256>>>(qkv_w, qkv_b);
    attn_kernel<<<dim3(BW, HEADS), 128>>>(rpb);
    gemm_proj_kernel<<<dim3(CCH / 64, MTOK / 64), 256>>>(proj_w, proj_b, out);
}

// round 2
// speedup vs baseline: 1.8381x; 1.8381x over previous
#include <cuda_runtime.h>
#include <cstdint>

// Problem constants
#define BATCH   32
#define HW      56
#define CCH     192
#define WS      7
#define NWIN1D  8
#define NW      49
#define BW      2048
#define HEADS   6
#define DH      32
#define MTOK    100352
#define QKV_N   576

// Scratch (device globals — allocation-free)
__device__ float g_xw[(size_t)BW * NW * CCH];             // LN'd, window-partitioned
__device__ float g_qkv[(size_t)3 * BW * HEADS * NW * DH]; // [s][w][h][n][d]
__device__ float g_att[(size_t)BW * NW * CCH];            // attention out, window order

__device__ __forceinline__ uint32_t f2tf32(float x) {
    uint32_t r;
    asm("cvt.rna.tf32.f32 %0, %1;" : "=r"(r) : "f"(x));
    return r;
}

__device__ __forceinline__ void mma_tf32(float c[4], const uint32_t a[4], const uint32_t b[2]) {
    asm volatile(
        "mma.sync.aligned.m16n8k8.row.col.f32.tf32.tf32.f32 "
        "{%0,%1,%2,%3}, {%4,%5,%6,%7}, {%8,%9}, {%0,%1,%2,%3};"
        : "+f"(c[0]), "+f"(c[1]), "+f"(c[2]), "+f"(c[3])
        : "r"(a[0]), "r"(a[1]), "r"(a[2]), "r"(a[3]), "r"(b[0]), "r"(b[1]));
}

// ---------------------------------------------------------------------------
// Kernel 1: LayerNorm + window partition. One warp per token.
// ---------------------------------------------------------------------------
__global__ void ln_partition_kernel(const float* __restrict__ x,
                                    const float* __restrict__ gamma) {
    int t    = blockIdx.x * 8 + (threadIdx.x >> 5);
    int lane = threadIdx.x & 31;
    const float* xp = x + (size_t)t * CCH;

    float v[6];
    float s = 0.f, sq = 0.f;
#pragma unroll
    for (int i = 0; i < 6; i++) {
        v[i] = xp[lane + 32 * i];
        s  += v[i];
        sq += v[i] * v[i];
    }
#pragma unroll
    for (int off = 16; off > 0; off >>= 1) {
        s  += __shfl_xor_sync(0xFFFFFFFFu, s,  off);
        sq += __shfl_xor_sync(0xFFFFFFFFu, sq, off);
    }
    float mu  = s  * (1.0f / CCH);
    float var = sq * (1.0f / CCH) - mu * mu;
    float rs  = rsqrtf(var + 1e-5f);

    int b  = t / 3136;
    int rc = t % 3136;
    int r  = rc / HW, c = rc % HW;
    int wr = r / WS, ir = r % WS;
    int wc = c / WS, ic = c % WS;
    int w  = (b * NWIN1D + wr) * NWIN1D + wc;
    int n  = ir * WS + ic;

    float* dst = g_xw + ((size_t)w * NW + n) * CCH;
#pragma unroll
    for (int i = 0; i < 6; i++) {
        int ch = lane + 32 * i;
        dst[ch] = (v[i] - mu) * rs * gamma[ch];
    }
}

// ---------------------------------------------------------------------------
// TF32 tensor-core GEMM: C[M, N] = A[M,192] @ W[N,192]^T + bias
// BM=128, BN=64, BK=32. 256 threads = 8 warps, warp tile 32x32.
// EPI 0: scatter into g_qkv; EPI 1: window-reverse scatter into out.
// ---------------------------------------------------------------------------
template <int EPI>
__global__ void __launch_bounds__(256) gemm_tf32_kernel(const float* __restrict__ A,
                                                        const float* __restrict__ W,
                                                        const float* __restrict__ bias,
                                                        float* __restrict__ out) {
    __shared__ uint32_t As[128][36];
    __shared__ uint32_t Bs[64][36];

    int tid  = threadIdx.x;
    int lane = tid & 31;
    int wid  = tid >> 5;
    int wm = wid & 3;      // 0..3  (m direction)
    int wn = wid >> 2;     // 0..1  (n direction)

    int bn = blockIdx.x;
    int bm = blockIdx.y;

    const float* Ag = A + (size_t)(bm * 128) * CCH;
    const float* Wg = W + (size_t)(bn * 64) * CCH;

    float acc[2][4][4] = {};

    for (int kt = 0; kt < CCH; kt += 32) {
        // Load A tile: 128 rows x 32 k = 1024 float4, 4 per thread
#pragma unroll
        for (int i = 0; i < 4; i++) {
            int q = tid + i * 256;
            int row = q >> 3;
            int kq  = q & 7;
            float4 f = *(const float4*)(Ag + (size_t)row * CCH + kt + kq * 4);
            As[row][kq * 4 + 0] = f2tf32(f.x);
            As[row][kq * 4 + 1] = f2tf32(f.y);
            As[row][kq * 4 + 2] = f2tf32(f.z);
            As[row][kq * 4 + 3] = f2tf32(f.w);
        }
        // Load B tile: 64 rows x 32 k = 512 float4, 2 per thread
#pragma unroll
        for (int i = 0; i < 2; i++) {
            int q = tid + i * 256;
            int row = q >> 3;
            int kq  = q & 7;
            float4 f = *(const float4*)(Wg + (size_t)row * CCH + kt + kq * 4);
            Bs[row][kq * 4 + 0] = f2tf32(f.x);
            Bs[row][kq * 4 + 1] = f2tf32(f.y);
            Bs[row][kq * 4 + 2] = f2tf32(f.z);
            Bs[row][kq * 4 + 3] = f2tf32(f.w);
        }
        __syncthreads();

#pragma unroll
        for (int ks = 0; ks < 32; ks += 8) {
            uint32_t af[2][4];
            uint32_t bf[4][2];
#pragma unroll
            for (int mt = 0; mt < 2; mt++) {
                int row = wm * 32 + mt * 16 + (lane >> 2);
                int k   = ks + (lane & 3);
                af[mt][0] = As[row][k];
                af[mt][1] = As[row + 8][k];
                af[mt][2] = As[row][k + 4];
                af[mt][3] = As[row + 8][k + 4];
            }
#pragma unroll
            for (int nt = 0; nt < 4; nt++) {
                int col = wn * 32 + nt * 8 + (lane >> 2);
                int k   = ks + (lane & 3);
                bf[nt][0] = Bs[col][k];
                bf[nt][1] = Bs[col][k + 4];
            }
#pragma unroll
            for (int mt = 0; mt < 2; mt++)
#pragma unroll
                for (int nt = 0; nt < 4; nt++)
                    mma_tf32(acc[mt][nt], af[mt], bf[nt]);
        }
        __syncthreads();
    }

    // Epilogue
#pragma unroll
    for (int mt = 0; mt < 2; mt++) {
#pragma unroll
        for (int nt = 0; nt < 4; nt++) {
#pragma unroll
            for (int e = 0; e < 4; e++) {
                int m  = bm * 128 + wm * 32 + mt * 16 + (lane >> 2) + (e >> 1) * 8;
                int jc = bn * 64 + wn * 32 + nt * 8 + (lane & 3) * 2 + (e & 1);
                float val = acc[mt][nt][e] + bias[jc];
                if (EPI == 0) {
                    int w = m / NW, n = m % NW;
                    int s    = jc / CCH;
                    int rem  = jc % CCH;
                    int head = rem / DH;
                    int dd   = rem % DH;
                    g_qkv[(((size_t)s * BW + w) * HEADS + head) * (NW * DH) + n * DH + dd] = val;
                } else {
                    int w = m / NW, n = m % NW;
                    int b  = w / 64;
                    int wr = (w % 64) / NWIN1D;
                    int wc = w % NWIN1D;
                    int r  = wr * WS + n / WS;
                    int c  = wc * WS + n % WS;
                    size_t t = (size_t)b * 3136 + (size_t)r * HW + c;
                    out[t * CCH + jc] = val;
                }
            }
        }
    }
}

// ---------------------------------------------------------------------------
// Kernel 3: attention per (window, head). 128 threads.
// ---------------------------------------------------------------------------
__global__ void __launch_bounds__(128) attn_kernel(const float* __restrict__ rpb) {
    int w    = blockIdx.x;
    int head = blockIdx.y;
    int tid  = threadIdx.x;
    int lane = tid & 31;
    int wid  = tid >> 5;

    __shared__ float qS[NW * 33];
    __shared__ float kS[NW * 33];
    __shared__ float vS[NW * 33];
    __shared__ float aS[NW * NW];
    __shared__ float biasS[169];

    size_t base = ((size_t)w * HEADS + head) * (NW * DH);
    const float* qg = g_qkv + base;
    const float* kg = g_qkv + (size_t)BW * HEADS * NW * DH + base;
    const float* vg = g_qkv + (size_t)2 * BW * HEADS * NW * DH + base;

    for (int i = tid; i < NW * DH; i += 128) {
        int n = i >> 5, c = i & 31;
        qS[n * 33 + c] = qg[i];
        kS[n * 33 + c] = kg[i];
        vS[n * 33 + c] = vg[i];
    }
    for (int i = tid; i < 169; i += 128) biasS[i] = rpb[i * HEADS + head];
    __syncthreads();

    const float scale = 0.17677669529663687f;
    int m0 = lane;
    int m1 = lane + 32;
    bool v1 = (m1 < NW);
    int m1c = v1 ? m1 : 0;
    int jr0 = m0 / WS, jc0 = m0 % WS;
    int jr1 = m1c / WS, jc1 = m1c % WS;

    for (int n = wid; n < NW; n += 4) {
        float a0 = 0.f, a1 = 0.f;
#pragma unroll
        for (int k = 0; k < DH; k++) {
            float qv = qS[n * 33 + k];
            a0 += qv * kS[m0 * 33 + k];
            a1 += qv * kS[m1c * 33 + k];
        }
        int ir = n / WS, ic = n % WS;
        float s0 = a0 * scale + biasS[(ir - jr0 + 6) * 13 + (ic - jc0 + 6)];
        float s1 = v1 ? (a1 * scale + biasS[(ir - jr1 + 6) * 13 + (ic - jc1 + 6)])
                      : -1e30f;
        float mx = fmaxf(s0, s1);
#pragma unroll
        for (int off = 16; off > 0; off >>= 1)
            mx = fmaxf(mx, __shfl_xor_sync(0xFFFFFFFFu, mx, off));
        float e0 = expf(s0 - mx);
        float e1 = v1 ? expf(s1 - mx) : 0.f;
        float sm = e0 + e1;
#pragma unroll
        for (int off = 16; off > 0; off >>= 1)
            sm += __shfl_xor_sync(0xFFFFFFFFu, sm, off);
        float inv = 1.0f / sm;
        aS[n * NW + m0] = e0 * inv;
        if (v1) aS[n * NW + m1] = e1 * inv;
    }
    __syncwarp();

    for (int n = wid; n < NW; n += 4) {
        float acc = 0.f;
#pragma unroll
        for (int m = 0; m < NW; m++)
            acc += aS[n * NW + m] * vS[m * 33 + lane];
        g_att[((size_t)w * NW + n) * CCH + head * DH + lane] = acc;
    }
}

// ---------------------------------------------------------------------------
extern "C" void kernel_launch(void* const* d_in, const int* in_sizes, int n_in,
                              void* d_out, int out_size) {
    const float* x      = (const float*)d_in[0];
    const float* gamma  = (const float*)d_in[1];
    const float* rpb    = (const float*)d_in[2];
    const float* qkv_w  = (const float*)d_in[3];
    const float* qkv_b  = (const float*)d_in[4];
    const float* proj_w = (const float*)d_in[5];
    const float* proj_b = (const float*)d_in[6];
    float* out = (float*)d_out;

    float* xw_ptr;  cudaGetSymbolAddress((void**)&xw_ptr, g_xw);
    float* att_ptr; cudaGetSymbolAddress((void**)&att_ptr, g_att);

    ln_partition_kernel<<<MTOK / 8, 256>>>(x, gamma);
    gemm_tf32_kernel<0><<<dim3(QKV_N / 64, MTOK / 128), 256>>>(xw_ptr, qkv_w, qkv_b, nullptr);
    attn_kernel<<<dim3(BW, HEADS), 128>>>(rpb);
    gemm_tf32_kernel<1><<<dim3(CCH / 64, MTOK / 128), 256>>>(att_ptr, proj_w, proj_b, out);
}